// round 2
// baseline (speedup 1.0000x reference)
#include <cuda_runtime.h>
#include <math.h>

#define B_  4
#define S_  2048
#define D_  1024
#define H_  16
#define HD_ 64
#define M_  (B_*S_)   // 8192 tokens

// Scratch (device-global: no runtime allocation allowed)
__device__ float g_q[M_*D_];    // [B,H,S,HD]
__device__ float g_k[M_*D_];    // [B,H,S,HD]
__device__ float g_v[M_*D_];    // [B,H,S,HD]
__device__ float g_att[M_*D_];  // [B,S,D] token-major
__device__ float g_y[M_*D_];    // [B,S,D] pre-LN

// ---------------------------------------------------------------------------
// GEMM: out = A @ W^T + bias (mode 0/1/2 -> q/k/v head layout; mode 3 -> y = .. + resid)
// A: [M_, D_], W: [D_, D_] row-major (out col n uses W row n). Tiles 64x64x16.
// ---------------------------------------------------------------------------
__global__ void __launch_bounds__(256) gemm_kernel(const float* __restrict__ A,
                                                   const float* __restrict__ W,
                                                   const float* __restrict__ bias,
                                                   const float* __restrict__ resid,
                                                   int mode)
{
    __shared__ float As[16][64];
    __shared__ float Bs[16][64];

    const float* Ap = (mode == 3) ? g_att : A;

    const int bm = blockIdx.y * 64;
    const int bn = blockIdx.x * 64;
    const int tid = threadIdx.x;
    const int tx = tid & 15, ty = tid >> 4;
    const int lr = tid >> 2, lq = tid & 3;

    float acc[4][4] = {};

    const float* Arow = Ap + (size_t)(bm + lr) * D_ + lq * 4;
    const float* Wrow = W  + (size_t)(bn + lr) * D_ + lq * 4;

    for (int k0 = 0; k0 < D_; k0 += 16) {
        float4 a = *(const float4*)(Arow + k0);
        float4 b = *(const float4*)(Wrow + k0);
        As[lq*4+0][lr] = a.x; As[lq*4+1][lr] = a.y;
        As[lq*4+2][lr] = a.z; As[lq*4+3][lr] = a.w;
        Bs[lq*4+0][lr] = b.x; Bs[lq*4+1][lr] = b.y;
        Bs[lq*4+2][lr] = b.z; Bs[lq*4+3][lr] = b.w;
        __syncthreads();
#pragma unroll
        for (int k = 0; k < 16; k++) {
            float4 av = *(const float4*)&As[k][ty*4];
            float4 bv = *(const float4*)&Bs[k][tx*4];
            float ar[4] = {av.x, av.y, av.z, av.w};
            float br[4] = {bv.x, bv.y, bv.z, bv.w};
#pragma unroll
            for (int i = 0; i < 4; i++)
#pragma unroll
                for (int j = 0; j < 4; j++)
                    acc[i][j] += ar[i] * br[j];
        }
        __syncthreads();
    }

#pragma unroll
    for (int i = 0; i < 4; i++) {
        const int row = bm + ty*4 + i;
#pragma unroll
        for (int j = 0; j < 4; j++) {
            const int col = bn + tx*4 + j;
            float v = acc[i][j] + bias[col];
            if (mode < 3) {
                float* outp = (mode == 0) ? g_q : (mode == 1) ? g_k : g_v;
                const int b = row / S_, s = row % S_;
                const int h = col / HD_, hd = col % HD_;
                outp[(((size_t)(b*H_ + h)) * S_ + s) * HD_ + hd] = v;
            } else {
                g_y[(size_t)row * D_ + col] = v + resid[(size_t)row * D_ + col];
            }
        }
    }
}

// ---------------------------------------------------------------------------
// Flash attention: one block per (bh, 64-query tile). KV tiles of 64.
// Online softmax: per-row m/l in registers, reduced over the 16 tx lanes.
// ---------------------------------------------------------------------------
__global__ void __launch_bounds__(256) attn_kernel(const int* __restrict__ mask)
{
    extern __shared__ float sm[];
    float* Qt = sm;              // [64][64], Qt[d*64 + r]   (d-major)
    float* Kt = sm + 4096;       // [64][64], Kt[d*64 + c]
    float* Vs = sm + 8192;       // [64][64], Vs[k*64 + c]
    float* Pt = sm + 12288;      // [64][65], Pt[k*65 + r]
    __shared__ int msk[64];

    const int bh = blockIdx.y;
    const int b  = bh >> 4;
    const int h  = bh & 15;
    const int q0 = blockIdx.x * 64;

    const float* Qg = g_q + (size_t)bh * S_ * HD_;
    const float* Kg = g_k + (size_t)bh * S_ * HD_;
    const float* Vg = g_v + (size_t)bh * S_ * HD_;

    const int tid = threadIdx.x;
    const int tx = tid & 15, ty = tid >> 4;
    const int lr = tid >> 2, lq = tid & 3;   // row 0..63, d-quarter 0..3

    {   // load full Q tile (64x64), transposed to d-major. 4 float4 per thread.
        const float* qrow = &Qg[(size_t)(q0 + lr) * HD_ + lq * 16];
#pragma unroll
        for (int c = 0; c < 4; c++) {
            const int d0 = lq * 16 + c * 4;
            float4 qv = *(const float4*)(qrow + c * 4);
            Qt[(d0+0)*64 + lr] = qv.x; Qt[(d0+1)*64 + lr] = qv.y;
            Qt[(d0+2)*64 + lr] = qv.z; Qt[(d0+3)*64 + lr] = qv.w;
        }
    }

    float mrow[4], lrow[4], o[4][4];
#pragma unroll
    for (int i = 0; i < 4; i++) {
        mrow[i] = -INFINITY; lrow[i] = 0.f;
#pragma unroll
        for (int j = 0; j < 4; j++) o[i][j] = 0.f;
    }

    for (int kt = 0; kt < S_; kt += 64) {
        {   // load full K (d-major) and V (k-major) 64x64 tiles
            const float* krow = &Kg[(size_t)(kt + lr) * HD_ + lq * 16];
            const float* vrow = &Vg[(size_t)(kt + lr) * HD_ + lq * 16];
#pragma unroll
            for (int c = 0; c < 4; c++) {
                const int d0 = lq * 16 + c * 4;
                float4 kv = *(const float4*)(krow + c * 4);
                Kt[(d0+0)*64 + lr] = kv.x; Kt[(d0+1)*64 + lr] = kv.y;
                Kt[(d0+2)*64 + lr] = kv.z; Kt[(d0+3)*64 + lr] = kv.w;
                float4 vv = *(const float4*)(vrow + c * 4);
                *(float4*)&Vs[lr*64 + d0] = vv;
            }
            if (tid < 64) msk[tid] = mask[b*S_ + kt + tid];
        }
        __syncthreads();

        // S = Q @ K^T
        float s[4][4] = {};
#pragma unroll 8
        for (int d = 0; d < 64; d++) {
            float4 qv4 = *(const float4*)&Qt[d*64 + ty*4];
            float4 kv4 = *(const float4*)&Kt[d*64 + tx*4];
            float qr[4] = {qv4.x, qv4.y, qv4.z, qv4.w};
            float kc[4] = {kv4.x, kv4.y, kv4.z, kv4.w};
#pragma unroll
            for (int i = 0; i < 4; i++)
#pragma unroll
                for (int j = 0; j < 4; j++)
                    s[i][j] += qr[i] * kc[j];
        }

        // scale + mask + online softmax update
        float pv[4][4];
#pragma unroll
        for (int i = 0; i < 4; i++) {
            float mx = -INFINITY;
#pragma unroll
            for (int j = 0; j < 4; j++) {
                float t = s[i][j] * 0.125f;           // 1/sqrt(64)
                if (msk[tx*4 + j] == 0) t = -10000.f;
                s[i][j] = t;
                mx = fmaxf(mx, t);
            }
#pragma unroll
            for (int off = 8; off; off >>= 1)
                mx = fmaxf(mx, __shfl_xor_sync(0xffffffffu, mx, off));
            const float mnew  = fmaxf(mrow[i], mx);
            const float alpha = __expf(mrow[i] - mnew);
            float ls = 0.f;
#pragma unroll
            for (int j = 0; j < 4; j++) {
                float p = __expf(s[i][j] - mnew);
                pv[i][j] = p; ls += p;
            }
#pragma unroll
            for (int off = 8; off; off >>= 1)
                ls += __shfl_xor_sync(0xffffffffu, ls, off);
            lrow[i] = lrow[i] * alpha + ls;
            mrow[i] = mnew;
#pragma unroll
            for (int j = 0; j < 4; j++) o[i][j] *= alpha;
        }

        // stage P transposed: Pt[k][r]
#pragma unroll
        for (int j = 0; j < 4; j++)
#pragma unroll
            for (int i = 0; i < 4; i++)
                Pt[(tx*4 + j)*65 + ty*4 + i] = pv[i][j];
        __syncthreads();

        // O += P @ V
#pragma unroll 4
        for (int k = 0; k < 64; k++) {
            float4 vc4 = *(const float4*)&Vs[k*64 + tx*4];
            float vc[4] = {vc4.x, vc4.y, vc4.z, vc4.w};
            float pr[4];
#pragma unroll
            for (int i = 0; i < 4; i++) pr[i] = Pt[k*65 + ty*4 + i];
#pragma unroll
            for (int i = 0; i < 4; i++)
#pragma unroll
                for (int j = 0; j < 4; j++)
                    o[i][j] += pr[i] * vc[j];
        }
        __syncthreads();
    }

    // epilogue: write [B,S,D] token-major
#pragma unroll
    for (int i = 0; i < 4; i++) {
        const float inv = 1.f / lrow[i];
        const int tok = b*S_ + q0 + ty*4 + i;
#pragma unroll
        for (int j = 0; j < 4; j++)
            g_att[(size_t)tok * D_ + h*HD_ + tx*4 + j] = o[i][j] * inv;
    }
}

// ---------------------------------------------------------------------------
// LayerNorm over last dim (1024), one block per token.
// ---------------------------------------------------------------------------
__global__ void __launch_bounds__(256) ln_kernel(const float* __restrict__ gamma,
                                                 const float* __restrict__ beta,
                                                 float* __restrict__ out)
{
    __shared__ float rs[8], rq[8];
    __shared__ float s_mu, s_rstd;

    const int row = blockIdx.x;
    const int tid = threadIdx.x;
    const float* yr = g_y + (size_t)row * D_;

    float4 val = *(const float4*)&yr[tid*4];
    float sum = val.x + val.y + val.z + val.w;
    float sq  = val.x*val.x + val.y*val.y + val.z*val.z + val.w*val.w;

#pragma unroll
    for (int off = 16; off; off >>= 1) {
        sum += __shfl_xor_sync(0xffffffffu, sum, off);
        sq  += __shfl_xor_sync(0xffffffffu, sq,  off);
    }
    const int wid = tid >> 5, lane = tid & 31;
    if (lane == 0) { rs[wid] = sum; rq[wid] = sq; }
    __syncthreads();
    if (tid == 0) {
        float ts = 0.f, tq = 0.f;
#pragma unroll
        for (int i = 0; i < 8; i++) { ts += rs[i]; tq += rq[i]; }
        const float mu  = ts / (float)D_;
        const float var = tq / (float)D_ - mu * mu;
        s_mu = mu;
        s_rstd = rsqrtf(var + 1e-5f);
    }
    __syncthreads();

    const float mu = s_mu, rstd = s_rstd;
    float4 g4 = *(const float4*)&gamma[tid*4];
    float4 b4 = *(const float4*)&beta[tid*4];
    float4 r;
    r.x = (val.x - mu) * rstd * g4.x + b4.x;
    r.y = (val.y - mu) * rstd * g4.y + b4.y;
    r.z = (val.z - mu) * rstd * g4.z + b4.z;
    r.w = (val.w - mu) * rstd * g4.w + b4.w;
    *(float4*)&out[(size_t)row * D_ + tid*4] = r;
}

// ---------------------------------------------------------------------------
extern "C" void kernel_launch(void* const* d_in, const int* in_sizes, int n_in,
                              void* d_out, int out_size)
{
    const float* x     = (const float*)d_in[0];
    // d_in[1]: template_ids (unused by reference math)
    const int*   mask  = (const int*)  d_in[2];
    const float* Wq    = (const float*)d_in[3];
    const float* bq    = (const float*)d_in[4];
    const float* Wk    = (const float*)d_in[5];
    const float* bk    = (const float*)d_in[6];
    const float* Wv    = (const float*)d_in[7];
    const float* bv    = (const float*)d_in[8];
    const float* Wo    = (const float*)d_in[9];
    const float* bo    = (const float*)d_in[10];
    const float* gamma = (const float*)d_in[11];
    const float* beta  = (const float*)d_in[12];
    float* out = (float*)d_out;

    const dim3 gg(D_/64, M_/64);   // 16 x 128

    gemm_kernel<<<gg, 256>>>(x, Wq, bq, x, 0);
    gemm_kernel<<<gg, 256>>>(x, Wk, bk, x, 1);
    gemm_kernel<<<gg, 256>>>(x, Wv, bv, x, 2);

    const int attn_smem = (4096*3 + 64*65) * (int)sizeof(float);  // 65792 B
    cudaFuncSetAttribute(attn_kernel, cudaFuncAttributeMaxDynamicSharedMemorySize,
                         attn_smem);
    attn_kernel<<<dim3(S_/64, B_*H_), 256, attn_smem>>>(mask);

    gemm_kernel<<<gg, 256>>>(x, Wo, bo, x, 3);
    ln_kernel<<<M_, 256>>>(gamma, beta, out);
}